// round 2
// baseline (speedup 1.0000x reference)
#include <cuda_runtime.h>

#define BB 8
#define TT 100
#define UU 64
#define ZZ 256   // 4U
#define PP 1000
#define NK 50
#define BT (BB*TT) // 800

// Scratch (__device__ globals — no allocation allowed)
__device__ __align__(16) float d_xk[BT*ZZ];   // xt @ lstm_kernel + bias
__device__ __align__(16) float d_ht[BT*UU];   // LSTM hidden states
__device__ __align__(16) float d_g[BT*NK];    // ht @ W1[0:64]
__device__ __align__(16) float d_XW[PP*52];   // X @ W1[64:192] + b1 (stride 52)

// ---------------------------------------------------------------------------
// Kernel 1: XW[p,k] = sum_j X[p,j]*W1[64+j,k] + b1[k]
// ---------------------------------------------------------------------------
__global__ void k_xw(const float* __restrict__ X, const float* __restrict__ W1,
                     const float* __restrict__ b1) {
    int p = blockIdx.x;
    int k = threadIdx.x;
    if (k >= NK) return;
    float acc = b1[k];
#pragma unroll 8
    for (int j = 0; j < 128; ++j)
        acc = fmaf(__ldg(&X[p*128 + j]), __ldg(&W1[(64 + j)*NK + k]), acc);
    d_XW[p*52 + k] = acc;
}

// ---------------------------------------------------------------------------
// Kernel 2: xk = xt @ lstm_kernel + bias, xt computed on the fly:
//   xt[row,i] = X[pid[row], i&127] * onehot[label[row], i]
// ---------------------------------------------------------------------------
__global__ void __launch_bounds__(256) k_gemm(
    const int* __restrict__ pro_id, const int* __restrict__ label,
    const float* __restrict__ X, const float* __restrict__ onehot,
    const float* __restrict__ Kmat, const float* __restrict__ bias) {
    __shared__ __align__(16) float sA[32][64];
    __shared__ __align__(16) float sB[32][64];

    int rowBase = blockIdx.x * 64;
    int n0      = blockIdx.y * 64;
    int tid = threadIdx.x;
    int ty = tid >> 4, tx = tid & 15;

    float acc[4][4];
#pragma unroll
    for (int r = 0; r < 4; ++r)
#pragma unroll
        for (int c = 0; c < 4; ++c) acc[r][c] = 0.f;

    for (int k0 = 0; k0 < 256; k0 += 32) {
#pragma unroll
        for (int q = 0; q < 2; ++q) {
            int idx = tid + q*256;        // 0..511
            int m   = idx >> 3;           // 0..63
            int kq  = (idx & 7) * 4;      // 0..28
            int row = rowBase + m;
            float4 v = make_float4(0.f, 0.f, 0.f, 0.f);
            if (row < BT) {
                int pid = pro_id[row];
                int lab = label[row];
                int i0 = k0 + kq;
                const float4 xv = *(const float4*)&X[pid*128 + (i0 & 127)];
                const float4 ov = *(const float4*)&onehot[lab*ZZ + i0];
                v = make_float4(xv.x*ov.x, xv.y*ov.y, xv.z*ov.z, xv.w*ov.w);
            }
            sA[kq+0][m] = v.x; sA[kq+1][m] = v.y; sA[kq+2][m] = v.z; sA[kq+3][m] = v.w;
        }
#pragma unroll
        for (int q = 0; q < 2; ++q) {
            int idx = tid + q*256;
            int kk  = idx >> 4;
            int n4  = (idx & 15) * 4;
            *(float4*)&sB[kk][n4] = *(const float4*)&Kmat[(k0 + kk)*256 + n0 + n4];
        }
        __syncthreads();
#pragma unroll
        for (int kk = 0; kk < 32; ++kk) {
            float4 a = *(const float4*)&sA[kk][ty*4];
            float4 b = *(const float4*)&sB[kk][tx*4];
            acc[0][0] = fmaf(a.x, b.x, acc[0][0]); acc[0][1] = fmaf(a.x, b.y, acc[0][1]);
            acc[0][2] = fmaf(a.x, b.z, acc[0][2]); acc[0][3] = fmaf(a.x, b.w, acc[0][3]);
            acc[1][0] = fmaf(a.y, b.x, acc[1][0]); acc[1][1] = fmaf(a.y, b.y, acc[1][1]);
            acc[1][2] = fmaf(a.y, b.z, acc[1][2]); acc[1][3] = fmaf(a.y, b.w, acc[1][3]);
            acc[2][0] = fmaf(a.z, b.x, acc[2][0]); acc[2][1] = fmaf(a.z, b.y, acc[2][1]);
            acc[2][2] = fmaf(a.z, b.z, acc[2][2]); acc[2][3] = fmaf(a.z, b.w, acc[2][3]);
            acc[3][0] = fmaf(a.w, b.x, acc[3][0]); acc[3][1] = fmaf(a.w, b.y, acc[3][1]);
            acc[3][2] = fmaf(a.w, b.z, acc[3][2]); acc[3][3] = fmaf(a.w, b.w, acc[3][3]);
        }
        __syncthreads();
    }
#pragma unroll
    for (int r = 0; r < 4; ++r) {
        int row = rowBase + ty*4 + r;
        if (row < BT) {
#pragma unroll
            for (int c = 0; c < 4; ++c) {
                int n = n0 + tx*4 + c;
                d_xk[row*ZZ + n] = acc[r][c] + __ldg(&bias[n]);
            }
        }
    }
}

// ---------------------------------------------------------------------------
// Kernel 3: LSTM recurrence. One block per batch; thread j owns column j of
// rec in registers. z = xk[t] + h @ rec, gates on threads 0..63.
// ---------------------------------------------------------------------------
__device__ __forceinline__ float sigf(float x) {
    return __fdividef(1.f, 1.f + __expf(-x));
}
__device__ __forceinline__ float tanhfast(float x) {
    return 1.f - __fdividef(2.f, __expf(2.f*x) + 1.f);
}

__global__ void __launch_bounds__(256) k_lstm(const float* __restrict__ rec) {
    int b = blockIdx.x;
    int j = threadIdx.x;
    float rc[64];
#pragma unroll
    for (int i = 0; i < 64; ++i) rc[i] = rec[i*ZZ + j];

    __shared__ __align__(16) float h_sh[64];
    __shared__ float z_sh[ZZ];
    if (j < 64) h_sh[j] = 0.f;
    float c = 0.f;
    __syncthreads();

#pragma unroll 1
    for (int t = 0; t < TT; ++t) {
        float z0 = d_xk[(b*TT + t)*ZZ + j];
        float z1 = 0.f, z2 = 0.f, z3 = 0.f;
        const float4* h4 = (const float4*)h_sh;
#pragma unroll
        for (int i0 = 0; i0 < 16; ++i0) {
            float4 hv = h4[i0];
            z0 = fmaf(hv.x, rc[4*i0+0], z0);
            z1 = fmaf(hv.y, rc[4*i0+1], z1);
            z2 = fmaf(hv.z, rc[4*i0+2], z2);
            z3 = fmaf(hv.w, rc[4*i0+3], z3);
        }
        z_sh[j] = (z0 + z1) + (z2 + z3);
        __syncthreads();
        if (j < 64) {
            float zi = z_sh[j], zf = z_sh[64+j], zg = z_sh[128+j], zo = z_sh[192+j];
            float ig = sigf(zi);
            float fg = sigf(zf);
            float gg = tanhfast(zg);
            float og = sigf(zo);
            c = fmaf(fg, c, ig*gg);
            float h = og * tanhfast(c);
            h_sh[j] = h;
            d_ht[(b*TT + t)*UU + j] = h;
        }
        __syncthreads();
    }
}

// ---------------------------------------------------------------------------
// Kernel 4: g[b,t,k] = sum_u ht[b,t,u] * W1[u,k]
// ---------------------------------------------------------------------------
__global__ void k_g(const float* __restrict__ W1) {
    int row = blockIdx.x;   // 0..799
    int k = threadIdx.x;
    if (k >= NK) return;
    float acc = 0.f;
#pragma unroll
    for (int u = 0; u < 64; ++u)
        acc = fmaf(d_ht[row*UU + u], __ldg(&W1[u*NK + k]), acc);
    d_g[row*NK + k] = acc;
}

// ---------------------------------------------------------------------------
// Kernel 5: main. Thread per (b,p). Suffix loop over t (tril => s>=t):
//   acc[k] += a[b,t,p] * g[b,t,k];  pred = relu(acc+XW[p])·W2 + b2
// ---------------------------------------------------------------------------
__global__ void __launch_bounds__(64) k_main(
    const int* __restrict__ pro_id, const float* __restrict__ cosX,
    const float* __restrict__ W2, const float* __restrict__ b2,
    float* __restrict__ out) {
    __shared__ __align__(16) float g_sh[TT*NK];   // 20 KB
    __shared__ int pid_sh[TT];

    int b   = blockIdx.y;
    int tid = threadIdx.x;
    int p   = blockIdx.x * 64 + tid;

    {
        const float4* gg = (const float4*)&d_g[b*TT*NK];
        float4* gs = (float4*)g_sh;
        for (int i = tid; i < (TT*NK)/4; i += 64) gs[i] = gg[i];
        for (int t = tid; t < TT; t += 64) pid_sh[t] = pro_id[b*TT + t];
    }
    __syncthreads();
    if (p >= PP) return;

    float acc[NK], xw[NK], w2[NK];
#pragma unroll
    for (int k = 0; k < NK; ++k) acc[k] = 0.f;
    {
        const float2* xw2 = (const float2*)&d_XW[p*52];
#pragma unroll
        for (int m = 0; m < 25; ++m) { float2 v = xw2[m]; xw[2*m] = v.x; xw[2*m+1] = v.y; }
    }
#pragma unroll
    for (int k = 0; k < NK; ++k) w2[k] = __ldg(&W2[k]);
    float b2v = __ldg(b2);

#pragma unroll 1
    for (int t = TT - 1; t >= 0; --t) {
        int rrow = pid_sh[t];
        float av = __ldg(&cosX[rrow*PP + p]);
        const float2* g2 = (const float2*)&g_sh[t*NK];
#pragma unroll
        for (int m = 0; m < 25; ++m) {
            float2 gv = g2[m];
            acc[2*m]   = fmaf(av, gv.x, acc[2*m]);
            acc[2*m+1] = fmaf(av, gv.y, acc[2*m+1]);
        }
        float d0 = 0.f, d1 = 0.f, d2 = 0.f, d3 = 0.f;
#pragma unroll
        for (int k = 0; k < 48; k += 4) {
            d0 = fmaf(fmaxf(acc[k]   + xw[k],   0.f), w2[k],   d0);
            d1 = fmaf(fmaxf(acc[k+1] + xw[k+1], 0.f), w2[k+1], d1);
            d2 = fmaf(fmaxf(acc[k+2] + xw[k+2], 0.f), w2[k+2], d2);
            d3 = fmaf(fmaxf(acc[k+3] + xw[k+3], 0.f), w2[k+3], d3);
        }
        d0 = fmaf(fmaxf(acc[48] + xw[48], 0.f), w2[48], d0);
        d1 = fmaf(fmaxf(acc[49] + xw[49], 0.f), w2[49], d1);
        out[(b*TT + t)*PP + p] = (d0 + d1) + (d2 + d3) + b2v;
    }
}

// ---------------------------------------------------------------------------
// Size-driven input resolution: immune to whether the scalar num_pro is
// passed and to metadata ordering among distinct-size tensors.
//   800x2 -> pro_id, label (decl order)   128000 -> X      1000000 -> cos_X
//   10000 -> trimatrix                    512    -> onehot 65536   -> kernel
//   16384 -> rec    256 -> bias   9600 -> W1   50x2 -> b1, W2 (decl order)
//   1: if two present, first=num_pro, last=b2; if one, it's b2.
// ---------------------------------------------------------------------------
extern "C" void kernel_launch(void* const* d_in, const int* in_sizes, int n_in,
                              void* d_out, int out_size) {
    const int *pro_id = 0, *label = 0;
    const float *X = 0, *cos_X = 0, *onehot = 0, *Kmat = 0, *rec = 0,
                *bias = 0, *W1 = 0, *b1 = 0, *W2 = 0, *b2 = 0;

    int n_ones = 0;
    for (int i = 0; i < n_in; ++i) if (in_sizes[i] == 1) n_ones++;
    int ones_seen = 0;

    for (int i = 0; i < n_in; ++i) {
        switch (in_sizes[i]) {
            case 800:     if (!pro_id) pro_id = (const int*)d_in[i];
                          else         label  = (const int*)d_in[i];      break;
            case 128000:  X      = (const float*)d_in[i];                 break;
            case 1000000: cos_X  = (const float*)d_in[i];                 break;
            case 10000:   /* trimatrix: tril(ones), hardcoded */          break;
            case 512:     onehot = (const float*)d_in[i];                 break;
            case 65536:   Kmat   = (const float*)d_in[i];                 break;
            case 16384:   rec    = (const float*)d_in[i];                 break;
            case 256:     bias   = (const float*)d_in[i];                 break;
            case 9600:    W1     = (const float*)d_in[i];                 break;
            case 50:      if (!b1) b1 = (const float*)d_in[i];
                          else     W2 = (const float*)d_in[i];            break;
            case 1:       ones_seen++;
                          // last size-1 entry is b2 (num_pro precedes it if present)
                          if (ones_seen == n_ones) b2 = (const float*)d_in[i];
                          break;
            default: break;
        }
    }

    float* out = (float*)d_out;

    k_xw  <<<PP, 64>>>(X, W1, b1);
    k_gemm<<<dim3(13, 4), 256>>>(pro_id, label, X, onehot, Kmat, bias);
    k_lstm<<<BB, 256>>>(rec);
    k_g   <<<BT, 64>>>(W1);
    k_main<<<dim3(16, BB), 64>>>(pro_id, cos_X, W2, b2, out);
}

// round 3
// speedup vs baseline: 1.2738x; 1.2738x over previous
#include <cuda_runtime.h>

typedef unsigned long long u64t;

#define BB 8
#define TT 100
#define UU 64
#define ZZ 256   // 4U
#define PP 1000
#define NK 50
#define NKP 56   // padded row: [0..24]=k0..24, [25..27]=0, [28..52]=k25..49, [53..55]=0
#define BT (BB*TT) // 800

// Scratch (__device__ globals — zero-initialized at load, no allocation)
__device__ __align__(16) float d_xk[BT*ZZ];        // xt @ lstm_kernel + bias
__device__ __align__(16) float d_g[BB*TT*NKP];     // ht @ W1[0:64], padded layout
__device__ __align__(16) float d_XW[1024*NKP];     // X @ W1[64:192] + b1, padded layout

// ---- packed f32x2 helpers (Blackwell) --------------------------------------
__device__ __forceinline__ u64t f2pk(float lo, float hi) {
    u64t r; asm("mov.b64 %0,{%1,%2};" : "=l"(r) : "f"(lo), "f"(hi)); return r;
}
__device__ __forceinline__ u64t ffma2(u64t a, u64t b, u64t c) {
    u64t d; asm("fma.rn.f32x2 %0,%1,%2,%3;" : "=l"(d) : "l"(a), "l"(b), "l"(c)); return d;
}
__device__ __forceinline__ u64t fadd2(u64t a, u64t b) {
    u64t d; asm("add.rn.f32x2 %0,%1,%2;" : "=l"(d) : "l"(a), "l"(b)); return d;
}
__device__ __forceinline__ float2 f2up(u64t v) {
    float2 r; asm("mov.b64 {%0,%1},%2;" : "=f"(r.x), "=f"(r.y) : "l"(v)); return r;
}

__device__ __forceinline__ float sigf(float x) {
    return __fdividef(1.f, 1.f + __expf(-x));
}
__device__ __forceinline__ float tanhfast(float x) {
    return 1.f - __fdividef(2.f, __expf(2.f*x) + 1.f);
}

// ---------------------------------------------------------------------------
// k_pre: blocks 0..103  -> xk GEMM (64x32 tiles, M=800, N=256, K=256)
//        blocks 104..353 -> XW[p,k] = X[p,:] @ W1b + b1 (4 p per block)
// ---------------------------------------------------------------------------
__global__ void __launch_bounds__(256) k_pre(
    const int* __restrict__ pro_id, const int* __restrict__ label,
    const float* __restrict__ X, const float* __restrict__ onehot,
    const float* __restrict__ Kmat, const float* __restrict__ bias,
    const float* __restrict__ W1, const float* __restrict__ b1) {
    __shared__ __align__(16) float sA[32][64];
    __shared__ __align__(16) float sB[32][32];
    int tid = threadIdx.x;
    int bx = blockIdx.x;

    if (bx < 104) {
        // ---- GEMM part ----
        int mblk = bx % 13, nblk = bx / 13;
        int rowBase = mblk * 64;
        int n0 = nblk * 32;
        int ty = tid >> 4, tx = tid & 15;   // rows ty*4.., cols tx*2..

        u64t acc2[2][2] = {{0ull,0ull},{0ull,0ull}};

        for (int k0 = 0; k0 < 256; k0 += 32) {
            // stage A (xt on the fly), transposed sA[k][m]
#pragma unroll
            for (int q = 0; q < 2; ++q) {
                int idx = tid + q*256;        // 0..511
                int m   = idx >> 3;           // 0..63
                int kq  = (idx & 7) * 4;      // 0..28
                int row = rowBase + m;
                float4 v = make_float4(0.f, 0.f, 0.f, 0.f);
                if (row < BT) {
                    int pid = pro_id[row];
                    int lab = label[row];
                    int i0 = k0 + kq;
                    const float4 xv = *(const float4*)&X[pid*128 + (i0 & 127)];
                    const float4 ov = *(const float4*)&onehot[lab*ZZ + i0];
                    v = make_float4(xv.x*ov.x, xv.y*ov.y, xv.z*ov.z, xv.w*ov.w);
                }
                sA[kq+0][m] = v.x; sA[kq+1][m] = v.y; sA[kq+2][m] = v.z; sA[kq+3][m] = v.w;
            }
            // stage B: 32x32 = 256 float4, one per thread
            {
                int kk = tid >> 3;
                int n4 = (tid & 7) * 4;
                *(float4*)&sB[kk][n4] = *(const float4*)&Kmat[(k0 + kk)*256 + n0 + n4];
            }
            __syncthreads();
#pragma unroll
            for (int kk = 0; kk < 32; ++kk) {
                longlong2 av = *(const longlong2*)&sA[kk][ty*4];  // m pairs (0,1),(2,3)
                float2 bv = *(const float2*)&sB[kk][tx*2];
                u64t b0 = f2pk(bv.x, bv.x);
                u64t b1p = f2pk(bv.y, bv.y);
                acc2[0][0] = ffma2((u64t)av.x, b0,  acc2[0][0]);
                acc2[1][0] = ffma2((u64t)av.y, b0,  acc2[1][0]);
                acc2[0][1] = ffma2((u64t)av.x, b1p, acc2[0][1]);
                acc2[1][1] = ffma2((u64t)av.y, b1p, acc2[1][1]);
            }
            __syncthreads();
        }
        // unpack + store with bias
        float bs0 = __ldg(&bias[n0 + tx*2]);
        float bs1 = __ldg(&bias[n0 + tx*2 + 1]);
#pragma unroll
        for (int mp = 0; mp < 2; ++mp) {
            float2 c0 = f2up(acc2[mp][0]);   // col tx*2,   rows (ty*4+2mp, +1)
            float2 c1 = f2up(acc2[mp][1]);   // col tx*2+1
            int r0 = rowBase + ty*4 + 2*mp;
            if (r0 < BT) {
                d_xk[r0*ZZ + n0 + tx*2]     = c0.x + bs0;
                d_xk[r0*ZZ + n0 + tx*2 + 1] = c1.x + bs1;
            }
            if (r0 + 1 < BT) {
                d_xk[(r0+1)*ZZ + n0 + tx*2]     = c0.y + bs0;
                d_xk[(r0+1)*ZZ + n0 + tx*2 + 1] = c1.y + bs1;
            }
        }
    } else {
        // ---- XW part ----
        int p = (bx - 104)*4 + (tid >> 6);
        int k = tid & 63;
        if (k < NK) {
            float acc = __ldg(&b1[k]);
#pragma unroll 8
            for (int j = 0; j < 128; ++j)
                acc = fmaf(__ldg(&X[p*128 + j]), __ldg(&W1[(64 + j)*NK + k]), acc);
            d_XW[p*NKP + ((k < 25) ? k : k + 3)] = acc;
        } else if (k < 56) {
            int off = (k >= 53) ? k : (k - 25);
            d_XW[p*NKP + off] = 0.f;
        }
    }
}

// ---------------------------------------------------------------------------
// k_lstm: one block per batch. Thread j owns column j of rec (packed f32x2).
// Prefetches xk; keeps h history in shared; epilogue computes g = ht @ W1a.
// ---------------------------------------------------------------------------
__global__ void __launch_bounds__(256) k_lstm(const float* __restrict__ rec,
                                              const float* __restrict__ W1) {
    int b = blockIdx.x;
    int j = threadIdx.x;
    __shared__ __align__(16) float h_hist[TT][UU];  // 25.6 KB
    __shared__ float z_sh[ZZ];

    u64t rc2[32];
#pragma unroll
    for (int m = 0; m < 32; ++m)
        rc2[m] = f2pk(rec[(2*m)*ZZ + j], rec[(2*m+1)*ZZ + j]);

    float c = 0.f;
    float xk_next = d_xk[(b*TT)*ZZ + j];

#pragma unroll 1
    for (int t = 0; t < TT; ++t) {
        float xk = xk_next;
        if (t + 1 < TT) xk_next = d_xk[(b*TT + t + 1)*ZZ + j];
        float z;
        if (t == 0) {
            z = xk;
        } else {
            const longlong2* h8 = (const longlong2*)h_hist[t-1];
            u64t z0 = f2pk(xk, 0.f), z1 = 0ull, z2 = 0ull, z3 = 0ull;
#pragma unroll
            for (int i = 0; i < 8; ++i) {
                longlong2 hA = h8[i], hB = h8[i+8];
                z0 = ffma2((u64t)hA.x, rc2[2*i],    z0);
                z1 = ffma2((u64t)hA.y, rc2[2*i+1],  z1);
                z2 = ffma2((u64t)hB.x, rc2[2*i+16], z2);
                z3 = ffma2((u64t)hB.y, rc2[2*i+17], z3);
            }
            float2 r = f2up(fadd2(fadd2(z0, z1), fadd2(z2, z3)));
            z = r.x + r.y;
        }
        z_sh[j] = z;
        __syncthreads();
        if (j < UU) {
            float zi = z_sh[j], zf = z_sh[64+j], zg = z_sh[128+j], zo = z_sh[192+j];
            float ig = sigf(zi);
            float fg = sigf(zf);
            float gg = tanhfast(zg);
            float og = sigf(zo);
            c = fmaf(fg, c, ig*gg);
            h_hist[t][j] = og * tanhfast(c);
        }
        __syncthreads();
    }

    // epilogue: g[b,t,k] = sum_u h_hist[t][u] * W1[u*50+k]  (padded store)
    int k = j & 63, tc = j >> 6;
    if (k < NK) {
        u64t w1c[32];
#pragma unroll
        for (int m = 0; m < 32; ++m)
            w1c[m] = f2pk(__ldg(&W1[(2*m)*NK + k]), __ldg(&W1[(2*m+1)*NK + k]));
        int off = (k < 25) ? k : k + 3;
#pragma unroll 1
        for (int tt = tc*25; tt < tc*25 + 25; ++tt) {
            const longlong2* h8 = (const longlong2*)h_hist[tt];
            u64t g0 = 0ull, g1 = 0ull, g2 = 0ull, g3 = 0ull;
#pragma unroll
            for (int i = 0; i < 8; ++i) {
                longlong2 hA = h8[i], hB = h8[i+8];
                g0 = ffma2((u64t)hA.x, w1c[2*i],    g0);
                g1 = ffma2((u64t)hA.y, w1c[2*i+1],  g1);
                g2 = ffma2((u64t)hB.x, w1c[2*i+16], g2);
                g3 = ffma2((u64t)hB.y, w1c[2*i+17], g3);
            }
            float2 r = f2up(fadd2(fadd2(g0, g1), fadd2(g2, g3)));
            d_g[(b*TT + tt)*NKP + off] = r.x + r.y;
        }
    } else if (k < 56) {
        int off = (k >= 53) ? k : (k - 25);
        for (int tt = tc*25; tt < tc*25 + 25; ++tt)
            d_g[(b*TT + tt)*NKP + off] = 0.f;
    }
}

// ---------------------------------------------------------------------------
// k_main: 128 threads, lane pairs split k (28+28 padded). acc init = xw.
//   acc[k] += a[b,t,p]*g[b,t,k]; pred = relu(acc)·W2 + b2  (suffix over t)
// ---------------------------------------------------------------------------
__global__ void __launch_bounds__(128) k_main(
    const int* __restrict__ pro_id, const float* __restrict__ cosX,
    const float* __restrict__ W2, const float* __restrict__ b2,
    float* __restrict__ out) {
    __shared__ __align__(16) float g_sh[TT*NKP];   // 22.4 KB
    __shared__ int pid_sh[TT];

    int b   = blockIdx.y;
    int tid = threadIdx.x;
    {
        const float4* gg = (const float4*)&d_g[b*TT*NKP];
        float4* gs = (float4*)g_sh;
        for (int i = tid; i < (TT*NKP)/4; i += 128) gs[i] = gg[i];
        for (int t = tid; t < TT; t += 128) pid_sh[t] = pro_id[b*TT + t];
    }
    __syncthreads();

    int p    = blockIdx.x*64 + (tid >> 1);
    int half = tid & 1;
    bool valid = (p < PP);
    int pc = valid ? p : (PP - 1);

    float acc[28], w2r[28];
    {
        const float4* x4 = (const float4*)&d_XW[p*NKP + half*28];
#pragma unroll
        for (int m = 0; m < 7; ++m) {
            float4 v = x4[m];
            acc[4*m] = v.x; acc[4*m+1] = v.y; acc[4*m+2] = v.z; acc[4*m+3] = v.w;
        }
    }
#pragma unroll
    for (int jj = 0; jj < 28; ++jj)
        w2r[jj] = (jj < 25) ? __ldg(&W2[half*25 + jj]) : 0.f;
    float b2v = __ldg(b2);

    float av = __ldg(&cosX[pid_sh[TT-1]*PP + pc]);
#pragma unroll 1
    for (int t = TT - 1; t >= 0; --t) {
        float avn = (t > 0) ? __ldg(&cosX[pid_sh[t-1]*PP + pc]) : 0.f;
        const float4* g4 = (const float4*)&g_sh[t*NKP + half*28];
#pragma unroll
        for (int m = 0; m < 7; ++m) {
            float4 gv = g4[m];
            acc[4*m]   = fmaf(av, gv.x, acc[4*m]);
            acc[4*m+1] = fmaf(av, gv.y, acc[4*m+1]);
            acc[4*m+2] = fmaf(av, gv.z, acc[4*m+2]);
            acc[4*m+3] = fmaf(av, gv.w, acc[4*m+3]);
        }
        float d0 = 0.f, d1 = 0.f, d2 = 0.f, d3 = 0.f;
#pragma unroll
        for (int jj = 0; jj < 28; jj += 4) {
            d0 = fmaf(fmaxf(acc[jj],   0.f), w2r[jj],   d0);
            d1 = fmaf(fmaxf(acc[jj+1], 0.f), w2r[jj+1], d1);
            d2 = fmaf(fmaxf(acc[jj+2], 0.f), w2r[jj+2], d2);
            d3 = fmaf(fmaxf(acc[jj+3], 0.f), w2r[jj+3], d3);
        }
        float d = (d0 + d1) + (d2 + d3);
        d += __shfl_xor_sync(0xffffffffu, d, 1);
        if (half == 0 && valid) out[(b*TT + t)*PP + p] = d + b2v;
        av = avn;
    }
}

// ---------------------------------------------------------------------------
// Size-driven input resolution (robust to scalar presence / ordering).
// ---------------------------------------------------------------------------
extern "C" void kernel_launch(void* const* d_in, const int* in_sizes, int n_in,
                              void* d_out, int out_size) {
    const int *pro_id = 0, *label = 0;
    const float *X = 0, *cos_X = 0, *onehot = 0, *Kmat = 0, *rec = 0,
                *bias = 0, *W1 = 0, *b1 = 0, *W2 = 0, *b2 = 0;

    int n_ones = 0;
    for (int i = 0; i < n_in; ++i) if (in_sizes[i] == 1) n_ones++;
    int ones_seen = 0;

    for (int i = 0; i < n_in; ++i) {
        switch (in_sizes[i]) {
            case 800:     if (!pro_id) pro_id = (const int*)d_in[i];
                          else         label  = (const int*)d_in[i];      break;
            case 128000:  X      = (const float*)d_in[i];                 break;
            case 1000000: cos_X  = (const float*)d_in[i];                 break;
            case 10000:   /* trimatrix: tril(ones), hardcoded */          break;
            case 512:     onehot = (const float*)d_in[i];                 break;
            case 65536:   Kmat   = (const float*)d_in[i];                 break;
            case 16384:   rec    = (const float*)d_in[i];                 break;
            case 256:     bias   = (const float*)d_in[i];                 break;
            case 9600:    W1     = (const float*)d_in[i];                 break;
            case 50:      if (!b1) b1 = (const float*)d_in[i];
                          else     W2 = (const float*)d_in[i];            break;
            case 1:       ones_seen++;
                          if (ones_seen == n_ones) b2 = (const float*)d_in[i];
                          break;
            default: break;
        }
    }

    float* out = (float*)d_out;

    k_pre <<<354, 256>>>(pro_id, label, X, onehot, Kmat, bias, W1, b1);
    k_lstm<<<BB, 256>>>(rec, W1);
    k_main<<<dim3(16, BB), 128>>>(pro_id, cos_X, W2, b2, out);
}

// round 4
// speedup vs baseline: 1.2820x; 1.0064x over previous
#include <cuda_runtime.h>

typedef unsigned long long u64t;

#define BB 8
#define TT 100
#define UU 64
#define ZZ 256   // 4U
#define PP 1000
#define NK 50
#define NKP 56   // padded row: [0..24]=k0..24, [25..27]=0, [28..52]=k25..49, [53..55]=0
#define BT (BB*TT) // 800

// Scratch (__device__ globals — zero-initialized at load, no allocation)
__device__ __align__(16) float d_xk[BT*ZZ];        // xt @ lstm_kernel + bias
__device__ __align__(16) float d_g[BB*TT*NKP];     // ht @ W1[0:64], padded layout
__device__ __align__(16) float d_XW[1024*NKP];     // X @ W1[64:192] + b1, padded layout

// ---- packed f32x2 helpers (Blackwell) --------------------------------------
__device__ __forceinline__ u64t f2pk(float lo, float hi) {
    u64t r; asm("mov.b64 %0,{%1,%2};" : "=l"(r) : "f"(lo), "f"(hi)); return r;
}
__device__ __forceinline__ u64t ffma2(u64t a, u64t b, u64t c) {
    u64t d; asm("fma.rn.f32x2 %0,%1,%2,%3;" : "=l"(d) : "l"(a), "l"(b), "l"(c)); return d;
}
__device__ __forceinline__ u64t fadd2(u64t a, u64t b) {
    u64t d; asm("add.rn.f32x2 %0,%1,%2;" : "=l"(d) : "l"(a), "l"(b)); return d;
}
__device__ __forceinline__ float2 f2up(u64t v) {
    float2 r; asm("mov.b64 {%0,%1},%2;" : "=f"(r.x), "=f"(r.y) : "l"(v)); return r;
}

__device__ __forceinline__ float sigf(float x) {
    return __fdividef(1.f, 1.f + __expf(-x));
}
__device__ __forceinline__ float tanhfast(float x) {
    return 1.f - __fdividef(2.f, __expf(2.f*x) + 1.f);
}

// ---------------------------------------------------------------------------
// k_pre: blocks 0..103  -> xk GEMM (64x32 tiles, M=800, N=256, K=256)
//        blocks 104..353 -> XW[p,k] = X[p,:] @ W1b + b1 (4 p per block)
// ---------------------------------------------------------------------------
__global__ void __launch_bounds__(256) k_pre(
    const int* __restrict__ pro_id, const int* __restrict__ label,
    const float* __restrict__ X, const float* __restrict__ onehot,
    const float* __restrict__ Kmat, const float* __restrict__ bias,
    const float* __restrict__ W1, const float* __restrict__ b1) {
    __shared__ __align__(16) float sA[32][64];
    __shared__ __align__(16) float sB[32][32];
    int tid = threadIdx.x;
    int bx = blockIdx.x;

    if (bx < 104) {
        // ---- GEMM part ----
        int mblk = bx % 13, nblk = bx / 13;
        int rowBase = mblk * 64;
        int n0 = nblk * 32;
        int ty = tid >> 4, tx = tid & 15;   // rows ty*4.., cols tx*2..

        u64t acc2[2][2] = {{0ull,0ull},{0ull,0ull}};

        for (int k0 = 0; k0 < 256; k0 += 32) {
            // stage A (xt on the fly), transposed sA[k][m]
#pragma unroll
            for (int q = 0; q < 2; ++q) {
                int idx = tid + q*256;        // 0..511
                int m   = idx >> 3;           // 0..63
                int kq  = (idx & 7) * 4;      // 0..28
                int row = rowBase + m;
                float4 v = make_float4(0.f, 0.f, 0.f, 0.f);
                if (row < BT) {
                    int pid = pro_id[row];
                    int lab = label[row];
                    int i0 = k0 + kq;
                    const float4 xv = *(const float4*)&X[pid*128 + (i0 & 127)];
                    const float4 ov = *(const float4*)&onehot[lab*ZZ + i0];
                    v = make_float4(xv.x*ov.x, xv.y*ov.y, xv.z*ov.z, xv.w*ov.w);
                }
                sA[kq+0][m] = v.x; sA[kq+1][m] = v.y; sA[kq+2][m] = v.z; sA[kq+3][m] = v.w;
            }
            // stage B: 32x32 = 256 float4, one per thread
            {
                int kk = tid >> 3;
                int n4 = (tid & 7) * 4;
                *(float4*)&sB[kk][n4] = *(const float4*)&Kmat[(k0 + kk)*256 + n0 + n4];
            }
            __syncthreads();
#pragma unroll
            for (int kk = 0; kk < 32; ++kk) {
                longlong2 av = *(const longlong2*)&sA[kk][ty*4];  // m pairs (0,1),(2,3)
                float2 bv = *(const float2*)&sB[kk][tx*2];
                u64t b0 = f2pk(bv.x, bv.x);
                u64t b1p = f2pk(bv.y, bv.y);
                acc2[0][0] = ffma2((u64t)av.x, b0,  acc2[0][0]);
                acc2[1][0] = ffma2((u64t)av.y, b0,  acc2[1][0]);
                acc2[0][1] = ffma2((u64t)av.x, b1p, acc2[0][1]);
                acc2[1][1] = ffma2((u64t)av.y, b1p, acc2[1][1]);
            }
            __syncthreads();
        }
        // unpack + store with bias
        float bs0 = __ldg(&bias[n0 + tx*2]);
        float bs1 = __ldg(&bias[n0 + tx*2 + 1]);
#pragma unroll
        for (int mp = 0; mp < 2; ++mp) {
            float2 c0 = f2up(acc2[mp][0]);   // col tx*2,   rows (ty*4+2mp, +1)
            float2 c1 = f2up(acc2[mp][1]);   // col tx*2+1
            int r0 = rowBase + ty*4 + 2*mp;
            if (r0 < BT) {
                d_xk[r0*ZZ + n0 + tx*2]     = c0.x + bs0;
                d_xk[r0*ZZ + n0 + tx*2 + 1] = c1.x + bs1;
            }
            if (r0 + 1 < BT) {
                d_xk[(r0+1)*ZZ + n0 + tx*2]     = c0.y + bs0;
                d_xk[(r0+1)*ZZ + n0 + tx*2 + 1] = c1.y + bs1;
            }
        }
    } else {
        // ---- XW part ----
        int p = (bx - 104)*4 + (tid >> 6);
        int k = tid & 63;
        if (k < NK) {
            float acc = __ldg(&b1[k]);
#pragma unroll 8
            for (int j = 0; j < 128; ++j)
                acc = fmaf(__ldg(&X[p*128 + j]), __ldg(&W1[(64 + j)*NK + k]), acc);
            d_XW[p*NKP + ((k < 25) ? k : k + 3)] = acc;
        } else if (k < 56) {
            int off = (k >= 53) ? k : (k - 25);
            d_XW[p*NKP + off] = 0.f;
        }
    }
}

// ---------------------------------------------------------------------------
// k_lstm: one block per batch. Thread j owns column j of rec (packed f32x2).
// Prefetches xk; keeps h history in shared; epilogue computes g = ht @ W1a.
// ---------------------------------------------------------------------------
__global__ void __launch_bounds__(256) k_lstm(const float* __restrict__ rec,
                                              const float* __restrict__ W1) {
    int b = blockIdx.x;
    int j = threadIdx.x;
    __shared__ __align__(16) float h_hist[TT][UU];  // 25.6 KB
    __shared__ float z_sh[ZZ];

    u64t rc2[32];
#pragma unroll
    for (int m = 0; m < 32; ++m)
        rc2[m] = f2pk(rec[(2*m)*ZZ + j], rec[(2*m+1)*ZZ + j]);

    float c = 0.f;
    float xk_next = d_xk[(b*TT)*ZZ + j];

#pragma unroll 1
    for (int t = 0; t < TT; ++t) {
        float xk = xk_next;
        if (t + 1 < TT) xk_next = d_xk[(b*TT + t + 1)*ZZ + j];
        float z;
        if (t == 0) {
            z = xk;
        } else {
            const longlong2* h8 = (const longlong2*)h_hist[t-1];
            u64t z0 = f2pk(xk, 0.f), z1 = 0ull, z2 = 0ull, z3 = 0ull;
#pragma unroll
            for (int i = 0; i < 8; ++i) {
                longlong2 hA = h8[i], hB = h8[i+8];
                z0 = ffma2((u64t)hA.x, rc2[2*i],    z0);
                z1 = ffma2((u64t)hA.y, rc2[2*i+1],  z1);
                z2 = ffma2((u64t)hB.x, rc2[2*i+16], z2);
                z3 = ffma2((u64t)hB.y, rc2[2*i+17], z3);
            }
            float2 r = f2up(fadd2(fadd2(z0, z1), fadd2(z2, z3)));
            z = r.x + r.y;
        }
        z_sh[j] = z;
        __syncthreads();
        if (j < UU) {
            float zi = z_sh[j], zf = z_sh[64+j], zg = z_sh[128+j], zo = z_sh[192+j];
            float ig = sigf(zi);
            float fg = sigf(zf);
            float gg = tanhfast(zg);
            float og = sigf(zo);
            c = fmaf(fg, c, ig*gg);
            h_hist[t][j] = og * tanhfast(c);
        }
        __syncthreads();
    }

    // epilogue: g[b,t,k] = sum_u h_hist[t][u] * W1[u*50+k]  (padded store)
    int k = j & 63, tc = j >> 6;
    if (k < NK) {
        u64t w1c[32];
#pragma unroll
        for (int m = 0; m < 32; ++m)
            w1c[m] = f2pk(__ldg(&W1[(2*m)*NK + k]), __ldg(&W1[(2*m+1)*NK + k]));
        int off = (k < 25) ? k : k + 3;
#pragma unroll 1
        for (int tt = tc*25; tt < tc*25 + 25; ++tt) {
            const longlong2* h8 = (const longlong2*)h_hist[tt];
            u64t g0 = 0ull, g1 = 0ull, g2 = 0ull, g3 = 0ull;
#pragma unroll
            for (int i = 0; i < 8; ++i) {
                longlong2 hA = h8[i], hB = h8[i+8];
                g0 = ffma2((u64t)hA.x, w1c[2*i],    g0);
                g1 = ffma2((u64t)hA.y, w1c[2*i+1],  g1);
                g2 = ffma2((u64t)hB.x, w1c[2*i+16], g2);
                g3 = ffma2((u64t)hB.y, w1c[2*i+17], g3);
            }
            float2 r = f2up(fadd2(fadd2(g0, g1), fadd2(g2, g3)));
            d_g[(b*TT + tt)*NKP + off] = r.x + r.y;
        }
    } else if (k < 56) {
        int off = (k >= 53) ? k : (k - 25);
        for (int tt = tc*25; tt < tc*25 + 25; ++tt)
            d_g[(b*TT + tt)*NKP + off] = 0.f;
    }
}

// ---------------------------------------------------------------------------
// k_main: 128 threads, lane pairs split k (28+28 padded). acc init = xw.
//   acc[k] += a[b,t,p]*g[b,t,k]; pred = relu(acc)·W2 + b2  (suffix over t)
// ---------------------------------------------------------------------------
__global__ void __launch_bounds__(128) k_main(
    const int* __restrict__ pro_id, const float* __restrict__ cosX,
    const float* __restrict__ W2, const float* __restrict__ b2,
    float* __restrict__ out) {
    __shared__ __align__(16) float g_sh[TT*NKP];   // 22.4 KB
    __shared__ int pid_sh[TT];

    int b   = blockIdx.y;
    int tid = threadIdx.x;
    {
        const float4* gg = (const float4*)&d_g[b*TT*NKP];
        float4* gs = (float4*)g_sh;
        for (int i = tid; i < (TT*NKP)/4; i += 128) gs[i] = gg[i];
        for (int t = tid; t < TT; t += 128) pid_sh[t] = pro_id[b*TT + t];
    }
    __syncthreads();

    int p    = blockIdx.x*64 + (tid >> 1);
    int half = tid & 1;
    bool valid = (p < PP);
    int pc = valid ? p : (PP - 1);

    float acc[28], w2r[28];
    {
        const float4* x4 = (const float4*)&d_XW[p*NKP + half*28];
#pragma unroll
        for (int m = 0; m < 7; ++m) {
            float4 v = x4[m];
            acc[4*m] = v.x; acc[4*m+1] = v.y; acc[4*m+2] = v.z; acc[4*m+3] = v.w;
        }
    }
#pragma unroll
    for (int jj = 0; jj < 28; ++jj)
        w2r[jj] = (jj < 25) ? __ldg(&W2[half*25 + jj]) : 0.f;
    float b2v = __ldg(b2);

    float av = __ldg(&cosX[pid_sh[TT-1]*PP + pc]);
#pragma unroll 1
    for (int t = TT - 1; t >= 0; --t) {
        float avn = (t > 0) ? __ldg(&cosX[pid_sh[t-1]*PP + pc]) : 0.f;
        const float4* g4 = (const float4*)&g_sh[t*NKP + half*28];
#pragma unroll
        for (int m = 0; m < 7; ++m) {
            float4 gv = g4[m];
            acc[4*m]   = fmaf(av, gv.x, acc[4*m]);
            acc[4*m+1] = fmaf(av, gv.y, acc[4*m+1]);
            acc[4*m+2] = fmaf(av, gv.z, acc[4*m+2]);
            acc[4*m+3] = fmaf(av, gv.w, acc[4*m+3]);
        }
        float d0 = 0.f, d1 = 0.f, d2 = 0.f, d3 = 0.f;
#pragma unroll
        for (int jj = 0; jj < 28; jj += 4) {
            d0 = fmaf(fmaxf(acc[jj],   0.f), w2r[jj],   d0);
            d1 = fmaf(fmaxf(acc[jj+1], 0.f), w2r[jj+1], d1);
            d2 = fmaf(fmaxf(acc[jj+2], 0.f), w2r[jj+2], d2);
            d3 = fmaf(fmaxf(acc[jj+3], 0.f), w2r[jj+3], d3);
        }
        float d = (d0 + d1) + (d2 + d3);
        d += __shfl_xor_sync(0xffffffffu, d, 1);
        if (half == 0 && valid) out[(b*TT + t)*PP + p] = d + b2v;
        av = avn;
    }
}

// ---------------------------------------------------------------------------
// Size-driven input resolution (robust to scalar presence / ordering).
// ---------------------------------------------------------------------------
extern "C" void kernel_launch(void* const* d_in, const int* in_sizes, int n_in,
                              void* d_out, int out_size) {
    const int *pro_id = 0, *label = 0;
    const float *X = 0, *cos_X = 0, *onehot = 0, *Kmat = 0, *rec = 0,
                *bias = 0, *W1 = 0, *b1 = 0, *W2 = 0, *b2 = 0;

    int n_ones = 0;
    for (int i = 0; i < n_in; ++i) if (in_sizes[i] == 1) n_ones++;
    int ones_seen = 0;

    for (int i = 0; i < n_in; ++i) {
        switch (in_sizes[i]) {
            case 800:     if (!pro_id) pro_id = (const int*)d_in[i];
                          else         label  = (const int*)d_in[i];      break;
            case 128000:  X      = (const float*)d_in[i];                 break;
            case 1000000: cos_X  = (const float*)d_in[i];                 break;
            case 10000:   /* trimatrix: tril(ones), hardcoded */          break;
            case 512:     onehot = (const float*)d_in[i];                 break;
            case 65536:   Kmat   = (const float*)d_in[i];                 break;
            case 16384:   rec    = (const float*)d_in[i];                 break;
            case 256:     bias   = (const float*)d_in[i];                 break;
            case 9600:    W1     = (const float*)d_in[i];                 break;
            case 50:      if (!b1) b1 = (const float*)d_in[i];
                          else     W2 = (const float*)d_in[i];            break;
            case 1:       ones_seen++;
                          if (ones_seen == n_ones) b2 = (const float*)d_in[i];
                          break;
            default: break;
        }
    }

    float* out = (float*)d_out;

    k_pre <<<354, 256>>>(pro_id, label, X, onehot, Kmat, bias, W1, b1);
    k_lstm<<<BB, 256>>>(rec, W1);
    k_main<<<dim3(16, BB), 128>>>(pro_id, cos_X, W2, b2, out);
}